// round 14
// baseline (speedup 1.0000x reference)
#include <cuda_runtime.h>
#include <cstdint>

#define B_    8
#define CIN   32
#define COUT  32
#define H_    96
#define W_    96
#define K_    5

#define TILE_X 32
#define TILE_Y 16
#define CCHUNK 4
#define ROWS   (TILE_Y + 4)

#define SCALE_F   2048.0f
#define INV_SCALE (1.0f / 2048.0f)
#define NEG_PACK  0x8AD08AD0u   // (-30000, -30000) as s16x2

#define NW_ELEMS  ((COUT / 8) * CIN * K_ * K_ * 8)   // 25600
#define NW_BLOCKS ((NW_ELEMS + 255) / 256)           // 100

// Dynamic smem (uint32 words):
//   sw   : 6400                (25.6 KB)
//   sf[2]: 2 x 3200 (sfe 1600 | sfo 1600)  (25.6 KB)
#define SW_WORDS   (CIN * 25 * 8)       // 6400
#define SFBUF      (CCHUNK * ROWS * 20) // 1600 per image
#define SMEM_WORDS (SW_WORDS + 2 * 2 * SFBUF)
#define SMEM_BYTES (SMEM_WORDS * 4)     // 51.2 KB

// Padded s16x2 f: [b][c][100 rows][64 words]; row r <-> gy = r-2, word w covers
// gx = (2w-2, 2w-1). Borders = NEG_PACK. 6.55 MB.
__device__ uint32_t g_fpad[B_][CIN][100][64];
// Pre-transposed duplicated weights: [o_group of 8][c][ij][o_local], (w,w) s16x2.
__device__ uint32_t g_w[COUT / 8][CIN][K_ * K_][8];

__device__ __forceinline__ uint32_t pack_s16x2(int a, int b) {
    return (uint32_t)(uint16_t)a | ((uint32_t)(uint16_t)b << 16);
}

// ---- Fused prep (identical to R8): blocks 0..1023 convert f; rest do weights.
__global__ __launch_bounds__(256) void prep_kernel(const float* __restrict__ f,
                                                   const float* __restrict__ h)
{
    const int bx  = blockIdx.x;
    const int tid = threadIdx.x;

    if (bx < 1024) {
        const int bc = bx >> 2;
        const int q  = bx & 3;
        const float* fp = f + (size_t)bc * (H_ * W_);
        uint32_t* dst = &g_fpad[0][0][0][0] + (size_t)bc * 6400;
        #pragma unroll
        for (int k = 0; k < 7; k++) {
            const int wi = q * 1600 + tid + k * 256;
            if (wi < (q + 1) * 1600) {
                const int ry = wi >> 6;
                const int cw = wi & 63;
                uint32_t v = NEG_PACK;
                if (ry >= 2 && ry < 98 && cw >= 1 && cw <= 48) {
                    const float2 t = *reinterpret_cast<const float2*>(
                        fp + (ry - 2) * W_ + (2 * cw - 2));
                    v = pack_s16x2(__float2int_rn(t.x * SCALE_F),
                                   __float2int_rn(t.y * SCALE_F));
                }
                dst[wi] = v;
            }
        }
    } else {
        const int idx = (bx - 1024) * 256 + tid;
        if (idx < NW_ELEMS) {
            const int og  = idx / (CIN * K_ * K_ * 8);
            const int rem = idx % (CIN * K_ * K_ * 8);
            const int c   = rem / (K_ * K_ * 8);
            const int r2  = rem % (K_ * K_ * 8);
            const int ij  = r2 >> 3;
            const int ol  = r2 & 7;
            const float wv =
                h[(size_t)(og * 8 + ol) * (CIN * K_ * K_) + c * (K_ * K_) + ij];
            const int wq = __float2int_rn(wv * SCALE_F);
            g_w[og][c][ij][ol] = pack_s16x2(wq, wq);
        }
    }
}

// ---- Main kernel (R8 + double-buffered single-barrier staging) ----
// 128 threads: xg = tid&3, tg = (tid>>2)&1, ty = tid>>3.
// Each thread: 8 px x 4 o = 32 outputs. Block: 8 o x 16 y x 32 x.
// Grid (3, 6, B*4) = 576 blocks, 4/SM, all co-resident.
__global__ __launch_bounds__(128) void dilate2d_dpx_kernel(float* __restrict__ out)
{
    extern __shared__ __align__(16) uint32_t smem[];
    uint32_t* sw  = smem;                     // [c][ij][o] : c*200 + ij*8 + o
    uint32_t* sfb = smem + SW_WORDS;          // buffer s at sfb + s*2*SFBUF

    const int tid = threadIdx.x;
    const int xg  = tid & 3;
    const int tg  = (tid >> 2) & 1;
    const int ty  = tid >> 3;

    const int bz = blockIdx.z;
    const int b  = bz >> 2;
    const int og = bz & 3;
    const int x0h = blockIdx.x * (TILE_X / 2);
    const int y0  = blockIdx.y * TILE_Y;

    // Staging role: threads 0..79 own one (cc, row) each.
    const bool stager = tid < CCHUNK * ROWS;
    const int scc = tid / ROWS;
    const int sr  = tid % ROWS;
    // Per-stager smem row bases (word offsets inside a buffer).
    const int rowoff = scc * (ROWS * 20) + sr * 20;

    // Stage one chunk into buffer s (R8's exact LDG + PRMT + STS sequence).
    auto stage = [&](int c0s, int s) {
        const uint4* src = reinterpret_cast<const uint4*>(
            &g_fpad[b][c0s + scc][y0 + sr][x0h]);
        uint32_t e[18];
        *reinterpret_cast<uint4*>(e)      = src[0];
        *reinterpret_cast<uint4*>(e + 4)  = src[1];
        *reinterpret_cast<uint4*>(e + 8)  = src[2];
        *reinterpret_cast<uint4*>(e + 12) = src[3];
        *reinterpret_cast<uint2*>(e + 16) = *reinterpret_cast<const uint2*>(src + 4);

        uint32_t* de = sfb + s * (2 * SFBUF) + rowoff;
        #pragma unroll
        for (int k = 0; k < 4; k++)
            reinterpret_cast<uint4*>(de)[k] = *reinterpret_cast<uint4*>(e + 4 * k);
        reinterpret_cast<uint2*>(de)[8] = *reinterpret_cast<uint2*>(e + 16);

        uint32_t o[17];
        #pragma unroll
        for (int k = 0; k < 17; k++)
            o[k] = __byte_perm(e[k], e[k + 1], 0x5432);
        uint32_t* do_ = de + SFBUF;
        #pragma unroll
        for (int k = 0; k < 4; k++)
            reinterpret_cast<uint4*>(do_)[k] = *reinterpret_cast<uint4*>(o + 4 * k);
        do_[16] = o[16];
    };

    // Weights: vector copy of this o-group's pre-transposed block (1600 uint4).
    {
        const uint4* src = reinterpret_cast<const uint4*>(&g_w[og][0][0][0]);
        uint4* dst = reinterpret_cast<uint4*>(sw);
        #pragma unroll
        for (int k = 0; k < 12; k++)
            dst[tid + k * 128] = src[tid + k * 128];
        if (tid < 64) dst[tid + 1536] = src[tid + 1536];
    }
    if (stager) stage(0, 0);
    __syncthreads();

    uint32_t acc[4][4];
    #pragma unroll
    for (int oo = 0; oo < 4; oo++)
        #pragma unroll
        for (int p = 0; p < 4; p++)
            acc[oo][p] = NEG_PACK;

    #pragma unroll 1
    for (int n = 0; n < CIN / CCHUNK; n++) {
        const int s  = n & 1;
        const int c0 = n * CCHUNK;

        // Stagers fill buffer s^1 with chunk n+1 while everyone computes from s.
        // Their LDG-wait overlaps other warps' DPX stream.
        if (n + 1 < CIN / CCHUNK && stager) stage(c0 + CCHUNK, s ^ 1);

        const uint32_t* sfe = sfb + s * (2 * SFBUF);
        const uint32_t* sfo = sfe + SFBUF;

        #pragma unroll
        for (int cc = 0; cc < CCHUNK; cc++) {
            const int c = c0 + cc;
            #pragma unroll
            for (int i = 0; i < K_; i++) {
                const uint32_t* rowE = sfe + cc * (ROWS * 20) + (ty + i) * 20 + xg * 4;
                const uint32_t* rowO = sfo + cc * (ROWS * 20) + (ty + i) * 20 + xg * 4;
                const uint4 ea = *reinterpret_cast<const uint4*>(rowE);
                const uint2 eb = *reinterpret_cast<const uint2*>(rowE + 4);
                const uint4 oa = *reinterpret_cast<const uint4*>(rowO);
                const uint32_t ob = rowO[4];
                const uint32_t eu[6] = { ea.x, ea.y, ea.z, ea.w, eb.x, eb.y };
                const uint32_t ou[5] = { oa.x, oa.y, oa.z, oa.w, ob };

                #pragma unroll
                for (int j = 0; j < K_; j++) {
                    const uint4 wr = *reinterpret_cast<const uint4*>(
                        sw + c * 200 + (i * K_ + j) * 8 + tg * 4);
                    const uint32_t w2[4] = { wr.x, wr.y, wr.z, wr.w };
                    #pragma unroll
                    for (int p = 0; p < 4; p++) {
                        const uint32_t fp = (j & 1) ? ou[((j - 1) >> 1) + p]
                                                    : eu[(j >> 1) + p];
                        #pragma unroll
                        for (int oo = 0; oo < 4; oo++)
                            acc[oo][p] = __viaddmax_s16x2(fp, w2[oo], acc[oo][p]);
                    }
                }
            }
        }
        __syncthreads();   // chunk n+1 fully staged; buffer s reusable
    }

    // Epilogue: s16 -> fp32 * (1/2048), 2 float4 stores per o.
    float* ob2 = out + ((size_t)b * COUT + og * 8 + tg * 4) * (H_ * W_)
               + (size_t)(y0 + ty) * W_ + blockIdx.x * TILE_X + xg * 8;
    #pragma unroll
    for (int oo = 0; oo < 4; oo++) {
        float* op = ob2 + (size_t)oo * (H_ * W_);
        float v[8];
        #pragma unroll
        for (int p = 0; p < 4; p++) {
            const uint32_t a = acc[oo][p];
            v[2 * p]     = (float)((int)(int16_t)(a & 0xFFFF)) * INV_SCALE;
            v[2 * p + 1] = (float)((int)(int16_t)(a >> 16))    * INV_SCALE;
        }
        reinterpret_cast<float4*>(op)[0] = make_float4(v[0], v[1], v[2], v[3]);
        reinterpret_cast<float4*>(op)[1] = make_float4(v[4], v[5], v[6], v[7]);
    }
}

extern "C" void kernel_launch(void* const* d_in, const int* in_sizes, int n_in,
                              void* d_out, int out_size)
{
    const float* f = (const float*)d_in[0];
    const float* h = (const float*)d_in[1];
    float* out = (float*)d_out;

    prep_kernel<<<1024 + NW_BLOCKS, 256>>>(f, h);

    cudaFuncSetAttribute(dilate2d_dpx_kernel,
                         cudaFuncAttributeMaxDynamicSharedMemorySize, SMEM_BYTES);
    dim3 grid(W_ / TILE_X, H_ / TILE_Y, B_ * 4);  // (3, 6, 32) = 576
    dilate2d_dpx_kernel<<<grid, 128, SMEM_BYTES>>>(out);
}

// round 15
// speedup vs baseline: 1.0069x; 1.0069x over previous
#include <cuda_runtime.h>
#include <cstdint>

#define B_    8
#define CIN   32
#define COUT  32
#define H_    96
#define W_    96
#define K_    5

#define TILE_X 32
#define TILE_Y 16
#define CCHUNK 4

#define SCALE_F   2048.0f
#define INV_SCALE (1.0f / 2048.0f)
#define NEG_PACK  0x8AD08AD0u   // (-30000, -30000) as s16x2

#define NW_ELEMS  ((COUT / 8) * CIN * K_ * K_ * 8)   // 25600
#define NW_BLOCKS ((NW_ELEMS + 255) / 256)           // 100

// Padded s16x2 f: [b][c][100 rows][64 words]; row r <-> gy = r-2, word w covers
// gx = (2w-2, 2w-1). Borders = NEG_PACK. 6.55 MB.
__device__ uint32_t g_fpad[B_][CIN][100][64];
// Pre-transposed duplicated weights: [o_group of 8][c][ij][o_local], (w,w) s16x2.
__device__ uint32_t g_w[COUT / 8][CIN][K_ * K_][8];

__device__ __forceinline__ uint32_t pack_s16x2(int a, int b) {
    return (uint32_t)(uint16_t)a | ((uint32_t)(uint16_t)b << 16);
}

// ---- Fused prep (R8): blocks 0..1023 convert f; blocks 1024..1123 do weights.
__global__ __launch_bounds__(256) void prep_kernel(const float* __restrict__ f,
                                                   const float* __restrict__ h)
{
    const int bx  = blockIdx.x;
    const int tid = threadIdx.x;

    if (bx < 1024) {
        const int bc = bx >> 2;            // b*32 + c
        const int q  = bx & 3;             // quarter of the 6400-word plane
        const float* fp = f + (size_t)bc * (H_ * W_);
        uint32_t* dst = &g_fpad[0][0][0][0] + (size_t)bc * 6400;
        #pragma unroll
        for (int k = 0; k < 7; k++) {
            const int wi = q * 1600 + tid + k * 256;
            if (wi < (q + 1) * 1600) {
                const int ry = wi >> 6;
                const int cw = wi & 63;
                uint32_t v = NEG_PACK;
                if (ry >= 2 && ry < 98 && cw >= 1 && cw <= 48) {
                    const float2 t = *reinterpret_cast<const float2*>(
                        fp + (ry - 2) * W_ + (2 * cw - 2));
                    v = pack_s16x2(__float2int_rn(t.x * SCALE_F),
                                   __float2int_rn(t.y * SCALE_F));
                }
                dst[wi] = v;
            }
        }
    } else {
        const int idx = (bx - 1024) * 256 + tid;
        if (idx < NW_ELEMS) {
            const int og  = idx / (CIN * K_ * K_ * 8);
            const int rem = idx % (CIN * K_ * K_ * 8);
            const int c   = rem / (K_ * K_ * 8);
            const int r2  = rem % (K_ * K_ * 8);
            const int ij  = r2 >> 3;
            const int ol  = r2 & 7;
            const float wv =
                h[(size_t)(og * 8 + ol) * (CIN * K_ * K_) + c * (K_ * K_) + ij];
            const int wq = __float2int_rn(wv * SCALE_F);
            g_w[og][c][ij][ol] = pack_s16x2(wq, wq);
        }
    }
}

// ---- Main kernel (R6 verbatim: rolled cc loop, small I-footprint body) ----
// 128 threads: xg = tid&3 (4 groups of 8 px), tg = (tid>>2)&1 (o half),
// ty = tid>>3 (16 rows). Each thread: 8 px x 4 o = 32 outputs.
// Block: 8 o x 16 y x 32 x. Grid (3, 6, B*4) = 576 (all co-resident, 4/SM).
__global__ __launch_bounds__(128) void dilate2d_dpx_kernel(float* __restrict__ out)
{
    __shared__ __align__(16) uint32_t sw[CIN][K_ * K_][8];         // 25.6 KB
    __shared__ __align__(16) uint32_t sfe[CCHUNK][TILE_Y + 4][20]; // aligned words
    __shared__ __align__(16) uint32_t sfo[CCHUNK][TILE_Y + 4][20]; // shifted 1 s16

    const int tid = threadIdx.x;
    const int xg  = tid & 3;
    const int tg  = (tid >> 2) & 1;
    const int ty  = tid >> 3;

    const int bz = blockIdx.z;
    const int b  = bz >> 2;
    const int og = bz & 3;
    const int x0h = blockIdx.x * (TILE_X / 2);
    const int y0  = blockIdx.y * TILE_Y;

    // Weights: vector copy of this o-group's pre-transposed block.
    {
        const uint4* src = reinterpret_cast<const uint4*>(&g_w[og][0][0][0]);
        uint4* dst = reinterpret_cast<uint4*>(&sw[0][0][0]);
        #pragma unroll
        for (int k = 0; k < 13; k++) {
            const int e = tid + k * 128;
            if (e < CIN * K_ * K_ * 2) dst[e] = src[e];
        }
    }

    uint32_t acc[4][4];
    #pragma unroll
    for (int oo = 0; oo < 4; oo++)
        #pragma unroll
        for (int p = 0; p < 4; p++)
            acc[oo][p] = NEG_PACK;

    #pragma unroll 1
    for (int c0 = 0; c0 < CIN; c0 += CCHUNK) {
        if (c0) __syncthreads();

        // Stage 4 channels x 20 rows: aligned copy + 1-s16-shifted copy.
        if (tid < CCHUNK * (TILE_Y + 4)) {
            const int cc = tid / (TILE_Y + 4);
            const int r  = tid % (TILE_Y + 4);
            const uint4* src = reinterpret_cast<const uint4*>(
                &g_fpad[b][c0 + cc][y0 + r][x0h]);
            uint32_t e[18];
            *reinterpret_cast<uint4*>(e)      = src[0];
            *reinterpret_cast<uint4*>(e + 4)  = src[1];
            *reinterpret_cast<uint4*>(e + 8)  = src[2];
            *reinterpret_cast<uint4*>(e + 12) = src[3];
            *reinterpret_cast<uint2*>(e + 16) = *reinterpret_cast<const uint2*>(src + 4);

            uint32_t* de = &sfe[cc][r][0];
            #pragma unroll
            for (int k = 0; k < 4; k++)
                reinterpret_cast<uint4*>(de)[k] = *reinterpret_cast<uint4*>(e + 4 * k);
            reinterpret_cast<uint2*>(de)[8] = *reinterpret_cast<uint2*>(e + 16);

            uint32_t o[17];
            #pragma unroll
            for (int k = 0; k < 17; k++)
                o[k] = __byte_perm(e[k], e[k + 1], 0x5432);
            uint32_t* do_ = &sfo[cc][r][0];
            #pragma unroll
            for (int k = 0; k < 4; k++)
                reinterpret_cast<uint4*>(do_)[k] = *reinterpret_cast<uint4*>(o + 4 * k);
            do_[16] = o[16];
        }
        __syncthreads();   // round 0 also publishes sw

        #pragma unroll 1
        for (int cc = 0; cc < CCHUNK; cc++) {
            const int c = c0 + cc;
            #pragma unroll
            for (int i = 0; i < K_; i++) {
                const uint32_t* rowE = &sfe[cc][ty + i][xg * 4];
                const uint32_t* rowO = &sfo[cc][ty + i][xg * 4];
                const uint4 ea = *reinterpret_cast<const uint4*>(rowE);
                const uint2 eb = *reinterpret_cast<const uint2*>(rowE + 4);
                const uint4 oa = *reinterpret_cast<const uint4*>(rowO);
                const uint32_t ob = rowO[4];
                const uint32_t eu[6] = { ea.x, ea.y, ea.z, ea.w, eb.x, eb.y };
                const uint32_t ou[5] = { oa.x, oa.y, oa.z, oa.w, ob };

                #pragma unroll
                for (int j = 0; j < K_; j++) {
                    const uint4 wr =
                        *reinterpret_cast<const uint4*>(&sw[c][i * K_ + j][tg * 4]);
                    const uint32_t w2[4] = { wr.x, wr.y, wr.z, wr.w };
                    #pragma unroll
                    for (int p = 0; p < 4; p++) {
                        const uint32_t fp = (j & 1) ? ou[((j - 1) >> 1) + p]
                                                    : eu[(j >> 1) + p];
                        #pragma unroll
                        for (int oo = 0; oo < 4; oo++)
                            acc[oo][p] = __viaddmax_s16x2(fp, w2[oo], acc[oo][p]);
                    }
                }
            }
        }
    }

    // Epilogue: s16 -> fp32 * (1/2048), 2 float4 stores per o.
    float* ob2 = out + ((size_t)b * COUT + og * 8 + tg * 4) * (H_ * W_)
               + (size_t)(y0 + ty) * W_ + blockIdx.x * TILE_X + xg * 8;
    #pragma unroll
    for (int oo = 0; oo < 4; oo++) {
        float* op = ob2 + (size_t)oo * (H_ * W_);
        float v[8];
        #pragma unroll
        for (int p = 0; p < 4; p++) {
            const uint32_t a = acc[oo][p];
            v[2 * p]     = (float)((int)(int16_t)(a & 0xFFFF)) * INV_SCALE;
            v[2 * p + 1] = (float)((int)(int16_t)(a >> 16))    * INV_SCALE;
        }
        reinterpret_cast<float4*>(op)[0] = make_float4(v[0], v[1], v[2], v[3]);
        reinterpret_cast<float4*>(op)[1] = make_float4(v[4], v[5], v[6], v[7]);
    }
}

extern "C" void kernel_launch(void* const* d_in, const int* in_sizes, int n_in,
                              void* d_out, int out_size)
{
    const float* f = (const float*)d_in[0];
    const float* h = (const float*)d_in[1];
    float* out = (float*)d_out;

    prep_kernel<<<1024 + NW_BLOCKS, 256>>>(f, h);

    dim3 grid(W_ / TILE_X, H_ / TILE_Y, B_ * 4);  // (3, 6, 32)
    dilate2d_dpx_kernel<<<grid, 128>>>(out);
}